// round 1
// baseline (speedup 1.0000x reference)
#include <cuda_runtime.h>
#include <math.h>

#define NB   8
#define TIN  2048
#define FIN  80
#define FOUT 128
#define TT   512
#define SEQ  624
#define DM   512
#define NH   8
#define HSZ  64
#define DFF  2048
#define RTOT 112
#define NLAYERS 4

// -------- scratch (static device globals; no allocations) --------
static __device__ float g_x  [NB*SEQ*DM];          // residual stream
static __device__ float g_y  [NB*SEQ*DM];          // LN output / attn context
static __device__ float g_q  [NB*SEQ*DM];
static __device__ float g_k  [NB*SEQ*DM];
static __device__ float g_v  [NB*SEQ*DM];
static __device__ float g_att[NB*NH*SEQ*SEQ];      // scores / probs
static __device__ float g_ffn[NB*SEQ*DFF];         // FFN hidden

// -------- Emformer mask, computed analytically --------
__device__ __forceinline__ bool emask(int qs, int ks) {
    int ci;
    if (qs < RTOT) {
        ci = qs >> 4;                       // ri = r / RIGHT
        if (ks < RTOT) return (ks >> 4) == ci;          // diag
    } else {
        ci = (qs - RTOT) >> 6;              // qi = q / CHUNK
        if (ks < RTOT) return ((ks >> 4) == ci) && (ci < 7);  // left
    }
    int k  = ks - RTOT;
    int lo = ci * 64 - 32; if (lo < 0)  lo = 0;
    int hi = (ci + 1) * 64; if (hi > TT) hi = TT;
    return (k >= lo) && (k < hi);           // right / body
}

// -------- block reductions --------
__device__ __forceinline__ float bsum(float v, float* sh) {
    int lane = threadIdx.x & 31, w = threadIdx.x >> 5;
    #pragma unroll
    for (int o = 16; o; o >>= 1) v += __shfl_xor_sync(0xffffffffu, v, o);
    if (lane == 0) sh[w] = v;
    __syncthreads();
    if (threadIdx.x < 32) {
        float t = (threadIdx.x < (blockDim.x >> 5)) ? sh[threadIdx.x] : 0.f;
        #pragma unroll
        for (int o = 16; o; o >>= 1) t += __shfl_xor_sync(0xffffffffu, t, o);
        if (threadIdx.x == 0) sh[0] = t;
    }
    __syncthreads();
    float r = sh[0];
    __syncthreads();
    return r;
}

__device__ __forceinline__ float bmax(float v, float* sh) {
    int lane = threadIdx.x & 31, w = threadIdx.x >> 5;
    #pragma unroll
    for (int o = 16; o; o >>= 1) v = fmaxf(v, __shfl_xor_sync(0xffffffffu, v, o));
    if (lane == 0) sh[w] = v;
    __syncthreads();
    if (threadIdx.x < 32) {
        float t = (threadIdx.x < (blockDim.x >> 5)) ? sh[threadIdx.x] : -3e38f;
        #pragma unroll
        for (int o = 16; o; o >>= 1) t = fmaxf(t, __shfl_xor_sync(0xffffffffu, t, o));
        if (threadIdx.x == 0) sh[0] = t;
    }
    __syncthreads();
    float r = sh[0];
    __syncthreads();
    return r;
}

// -------- input dense + stack-subsample + right-context gather --------
// grid (SEQ, NB), 128 threads. Writes x[b, s, :].
__global__ void k_input(const float* __restrict__ audio,
                        const float* __restrict__ W,
                        const float* __restrict__ bias,
                        float* __restrict__ x) {
    int b = blockIdx.y, s = blockIdx.x;
    int t = (s < RTOT) ? (((s >> 4) + 1) * 64 + (s & 15)) : (s - RTOT);
    __shared__ float sa[4 * FIN];
    const float* arow = audio + ((long long)b * TIN + t * 4) * FIN;
    for (int i = threadIdx.x; i < 4 * FIN; i += 128) sa[i] = arow[i];
    __syncthreads();
    int fo = threadIdx.x;                 // 0..127
    float* xr = x + ((long long)b * SEQ + s) * DM;
    #pragma unroll
    for (int sub = 0; sub < 4; sub++) {
        float acc = bias[fo];
        #pragma unroll 8
        for (int f = 0; f < FIN; f++) acc += sa[sub * FIN + f] * W[f * FOUT + fo];
        xr[sub * FOUT + fo] = acc;
    }
}

// -------- LayerNorm (optionally fused residual add), 1 row / block, 256 thr --------
__global__ void k_ln(const float* __restrict__ in, const float* __restrict__ add,
                     float* __restrict__ out,
                     const float* __restrict__ gg, const float* __restrict__ bb) {
    __shared__ float sh[32];
    long long base = (long long)blockIdx.x * DM;
    int t = threadIdx.x;
    float v0 = in[base + t], v1 = in[base + t + 256];
    if (add) { v0 += add[base + t]; v1 += add[base + t + 256]; }
    float mu  = bsum(v0 + v1, sh) * (1.f / DM);
    float d0 = v0 - mu, d1 = v1 - mu;
    float var = bsum(d0 * d0 + d1 * d1, sh) * (1.f / DM);
    float r = rsqrtf(var + 1e-3f);
    out[base + t]       = d0 * r * gg[t]       + bb[t];
    out[base + t + 256] = d1 * r * gg[t + 256] + bb[t + 256];
}

// -------- row softmax over SEQ, 1 row / block --------
__global__ void k_softmax(float* __restrict__ att) {
    __shared__ float sh[32];
    float* row = att + (long long)blockIdx.x * SEQ;
    float m = -3e38f;
    for (int i = threadIdx.x; i < SEQ; i += 256) m = fmaxf(m, row[i]);
    m = bmax(m, sh);
    float s = 0.f;
    for (int i = threadIdx.x; i < SEQ; i += 256) {
        float e = __expf(row[i] - m);
        row[i] = e; s += e;
    }
    s = bsum(s, sh);
    float inv = 1.f / s;
    for (int i = threadIdx.x; i < SEQ; i += 256) row[i] *= inv;
}

// -------- generic tiled GEMM: C = epilogue(alpha * A@B(^T) + bias) --------
// 64x64 tile, 256 threads, 4x4 per thread, K-tile 16. Batched via blockIdx.z.
// mode: 0 store, 1 accumulate into C, 2 relu, 3 attention scale+mask epilogue.
__global__ void k_gemm(const float* __restrict__ A, int lda, long long sAb, long long sAh,
                       const float* __restrict__ B, int ldb, long long sBb, long long sBh,
                       float* __restrict__ C, int ldc, long long sCb, long long sCh,
                       const float* __restrict__ bias,
                       int M, int N, int K, int Hdiv, int mode, float alpha, int transB) {
    __shared__ float As[16][64];
    __shared__ float Bs[16][64];
    int bz = blockIdx.z;
    int bb = bz / Hdiv, hh = bz % Hdiv;
    A += bb * sAb + hh * sAh;
    B += bb * sBb + hh * sBh;
    C += bb * sCb + hh * sCh;

    int tid = threadIdx.x;
    int tx = tid & 15, ty = tid >> 4;
    int rowA = blockIdx.y * 64 + (tid >> 2);
    int ka0  = (tid & 3) * 4;

    float acc[4][4];
    #pragma unroll
    for (int i = 0; i < 4; i++)
        #pragma unroll
        for (int j = 0; j < 4; j++) acc[i][j] = 0.f;

    for (int k0 = 0; k0 < K; k0 += 16) {
        #pragma unroll
        for (int j = 0; j < 4; j++) {
            int kk = k0 + ka0 + j;
            As[ka0 + j][tid >> 2] = (rowA < M && kk < K) ? A[(long long)rowA * lda + kk] : 0.f;
        }
        if (!transB) {
            int kb = tid >> 4, nb = (tid & 15) * 4;
            #pragma unroll
            for (int j = 0; j < 4; j++) {
                int n = blockIdx.x * 64 + nb + j;
                Bs[kb][nb + j] = (k0 + kb < K && n < N) ? B[(long long)(k0 + kb) * ldb + n] : 0.f;
            }
        } else {
            int nb = tid >> 2, kb0 = (tid & 3) * 4;
            int n = blockIdx.x * 64 + nb;
            #pragma unroll
            for (int j = 0; j < 4; j++) {
                int kk = k0 + kb0 + j;
                Bs[kb0 + j][nb] = (n < N && kk < K) ? B[(long long)n * ldb + kk] : 0.f;
            }
        }
        __syncthreads();
        #pragma unroll
        for (int k = 0; k < 16; k++) {
            float a[4], bv[4];
            #pragma unroll
            for (int i = 0; i < 4; i++) a[i] = As[k][ty * 4 + i];
            #pragma unroll
            for (int j = 0; j < 4; j++) bv[j] = Bs[k][tx * 4 + j];
            #pragma unroll
            for (int i = 0; i < 4; i++)
                #pragma unroll
                for (int j = 0; j < 4; j++) acc[i][j] += a[i] * bv[j];
        }
        __syncthreads();
    }

    #pragma unroll
    for (int i = 0; i < 4; i++) {
        int row = blockIdx.y * 64 + ty * 4 + i;
        if (row >= M) continue;
        #pragma unroll
        for (int j = 0; j < 4; j++) {
            int col = blockIdx.x * 64 + tx * 4 + j;
            if (col >= N) continue;
            float v = acc[i][j] * alpha;
            if (bias) v += bias[col];
            long long ci = (long long)row * ldc + col;
            if (mode == 0)      C[ci] = v;
            else if (mode == 1) C[ci] += v;
            else if (mode == 2) C[ci] = fmaxf(v, 0.f);
            else                C[ci] = emask(row, col) ? v : -1e9f;
        }
    }
}

// -------- final slice [B, RTOT:, :] -> out --------
__global__ void k_out(const float* __restrict__ x, float* __restrict__ out) {
    int idx = blockIdx.x * 256 + threadIdx.x;       // B*TT*DM total
    int d = idx & (DM - 1);
    int t = (idx >> 9) & (TT - 1);
    int b = idx >> 18;
    out[idx] = x[((long long)b * SEQ + RTOT + t) * DM + d];
}

extern "C" void kernel_launch(void* const* d_in, const int* in_sizes, int n_in,
                              void* d_out, int out_size) {
    const float* audio   = (const float*)d_in[0];
    const float* W_in    = (const float*)d_in[1];
    const float* b_in    = (const float*)d_in[2];
    const float* ln_in_g = (const float*)d_in[3];
    const float* ln_in_b = (const float*)d_in[4];
    const float* Wq = (const float*)d_in[5];
    const float* bq = (const float*)d_in[6];
    const float* Wk = (const float*)d_in[7];
    const float* bk = (const float*)d_in[8];
    const float* Wv = (const float*)d_in[9];
    const float* bv = (const float*)d_in[10];
    const float* Wo = (const float*)d_in[11];
    const float* bo = (const float*)d_in[12];
    const float* ln1_g = (const float*)d_in[13];
    const float* ln1_b = (const float*)d_in[14];
    const float* W1 = (const float*)d_in[15];
    const float* b1 = (const float*)d_in[16];
    const float* W2 = (const float*)d_in[17];
    const float* b2 = (const float*)d_in[18];
    const float* ln2_g = (const float*)d_in[19];
    const float* ln2_b = (const float*)d_in[20];
    (void)in_sizes; (void)n_in; (void)out_size;

    float *x, *y, *qb, *kb, *vb, *att, *ffn;
    cudaGetSymbolAddress((void**)&x,   g_x);
    cudaGetSymbolAddress((void**)&y,   g_y);
    cudaGetSymbolAddress((void**)&qb,  g_q);
    cudaGetSymbolAddress((void**)&kb,  g_k);
    cudaGetSymbolAddress((void**)&vb,  g_v);
    cudaGetSymbolAddress((void**)&att, g_att);
    cudaGetSymbolAddress((void**)&ffn, g_ffn);

    const int M = NB * SEQ;                           // 4992
    const long long sBD = (long long)SEQ * DM;        // per-batch stride in q/k/v/y
    const long long sAttB = (long long)NH * SEQ * SEQ;
    const long long sAttH = (long long)SEQ * SEQ;

    k_input<<<dim3(SEQ, NB), 128>>>(audio, W_in, b_in, x);

    for (int l = 0; l < NLAYERS; l++) {
        const float* wq = Wq + (long long)l * DM * DM;
        const float* wk = Wk + (long long)l * DM * DM;
        const float* wv = Wv + (long long)l * DM * DM;
        const float* wo = Wo + (long long)l * DM * DM;
        const float* w1 = W1 + (long long)l * DM * DFF;
        const float* w2 = W2 + (long long)l * DFF * DM;

        // pre-attention LN
        k_ln<<<M, 256>>>(x, nullptr, y, ln_in_g + l * DM, ln_in_b + l * DM);

        // QKV projections
        k_gemm<<<dim3(8, 78, 1), 256>>>(y, DM, 0, 0, wq, DM, 0, 0, qb, DM, 0, 0,
                                        bq + l * DM, M, DM, DM, 1, 0, 1.f, 0);
        k_gemm<<<dim3(8, 78, 1), 256>>>(y, DM, 0, 0, wk, DM, 0, 0, kb, DM, 0, 0,
                                        bk + l * DM, M, DM, DM, 1, 0, 1.f, 0);
        k_gemm<<<dim3(8, 78, 1), 256>>>(y, DM, 0, 0, wv, DM, 0, 0, vb, DM, 0, 0,
                                        bv + l * DM, M, DM, DM, 1, 0, 1.f, 0);

        // scores = (Q @ K^T) * 1/8, masked   [B*H batched 624x624x64]
        k_gemm<<<dim3(10, 10, NB * NH), 256>>>(qb, DM, sBD, HSZ, kb, DM, sBD, HSZ,
                                               att, SEQ, sAttB, sAttH,
                                               nullptr, SEQ, SEQ, HSZ, NH, 3, 0.125f, 1);
        k_softmax<<<NB * NH * SEQ, 256>>>(att);

        // context = P @ V  -> y   [B*H batched 624x64x624]
        k_gemm<<<dim3(1, 10, NB * NH), 256>>>(att, SEQ, sAttB, sAttH, vb, DM, sBD, HSZ,
                                              y, DM, sBD, HSZ,
                                              nullptr, SEQ, HSZ, SEQ, NH, 0, 1.f, 0);

        // x += ctx @ Wo + bo
        k_gemm<<<dim3(8, 78, 1), 256>>>(y, DM, 0, 0, wo, DM, 0, 0, x, DM, 0, 0,
                                        bo + l * DM, M, DM, DM, 1, 1, 1.f, 0);

        // FFN
        k_ln<<<M, 256>>>(x, nullptr, y, ln1_g + l * DM, ln1_b + l * DM);
        k_gemm<<<dim3(32, 78, 1), 256>>>(y, DM, 0, 0, w1, DFF, 0, 0, ffn, DFF, 0, 0,
                                         b1 + l * DFF, M, DFF, DM, 1, 2, 1.f, 0);
        k_gemm<<<dim3(8, 78, 1), 256>>>(ffn, DFF, 0, 0, w2, DM, 0, 0, qb, DM, 0, 0,
                                        b2 + l * DM, M, DM, DFF, 1, 0, 1.f, 0);

        // x = LN(x + ffn_out)
        k_ln<<<M, 256>>>(x, qb, x, ln2_g + l * DM, ln2_b + l * DM);
    }

    k_out<<<(NB * TT * DM) / 256, 256>>>(x, (float*)d_out);
}

// round 2
// speedup vs baseline: 3.2385x; 3.2385x over previous
#include <cuda_runtime.h>
#include <math.h>

#define NB   8
#define TIN  2048
#define FIN  80
#define FOUT 128
#define TT   512
#define SEQ  624
#define DM   512
#define NH   8
#define HSZ  64
#define DFF  2048
#define RTOT 112
#define NLAYERS 4

// -------- scratch (static device globals; no allocations) --------
static __device__ float g_x  [NB*SEQ*DM];
static __device__ float g_y  [NB*SEQ*DM];
static __device__ float g_q  [NB*SEQ*DM];
static __device__ float g_k  [NB*SEQ*DM];
static __device__ float g_v  [NB*SEQ*DM];
static __device__ float g_att[NB*NH*SEQ*SEQ];
static __device__ float g_ffn[NB*SEQ*DFF];

// -------- Emformer mask, computed analytically --------
__device__ __forceinline__ bool emask(int qs, int ks) {
    int ci;
    if (qs < RTOT) {
        ci = qs >> 4;
        if (ks < RTOT) return (ks >> 4) == ci;
    } else {
        ci = (qs - RTOT) >> 6;
        if (ks < RTOT) return ((ks >> 4) == ci) && (ci < 7);
    }
    int k  = ks - RTOT;
    int lo = ci * 64 - 32; if (lo < 0)  lo = 0;
    int hi = (ci + 1) * 64; if (hi > TT) hi = TT;
    return (k >= lo) && (k < hi);
}

// -------- block reductions --------
__device__ __forceinline__ float bsum(float v, float* sh) {
    int lane = threadIdx.x & 31, w = threadIdx.x >> 5;
    #pragma unroll
    for (int o = 16; o; o >>= 1) v += __shfl_xor_sync(0xffffffffu, v, o);
    if (lane == 0) sh[w] = v;
    __syncthreads();
    if (threadIdx.x < 32) {
        float t = (threadIdx.x < (blockDim.x >> 5)) ? sh[threadIdx.x] : 0.f;
        #pragma unroll
        for (int o = 16; o; o >>= 1) t += __shfl_xor_sync(0xffffffffu, t, o);
        if (threadIdx.x == 0) sh[0] = t;
    }
    __syncthreads();
    float r = sh[0];
    __syncthreads();
    return r;
}

__device__ __forceinline__ float bmax(float v, float* sh) {
    int lane = threadIdx.x & 31, w = threadIdx.x >> 5;
    #pragma unroll
    for (int o = 16; o; o >>= 1) v = fmaxf(v, __shfl_xor_sync(0xffffffffu, v, o));
    if (lane == 0) sh[w] = v;
    __syncthreads();
    if (threadIdx.x < 32) {
        float t = (threadIdx.x < (blockDim.x >> 5)) ? sh[threadIdx.x] : -3e38f;
        #pragma unroll
        for (int o = 16; o; o >>= 1) t = fmaxf(t, __shfl_xor_sync(0xffffffffu, t, o));
        if (threadIdx.x == 0) sh[0] = t;
    }
    __syncthreads();
    float r = sh[0];
    __syncthreads();
    return r;
}

// -------- input dense + stack-subsample + right-context gather --------
__global__ void k_input(const float* __restrict__ audio,
                        const float* __restrict__ W,
                        const float* __restrict__ bias,
                        float* __restrict__ x) {
    int b = blockIdx.y, s = blockIdx.x;
    int t = (s < RTOT) ? (((s >> 4) + 1) * 64 + (s & 15)) : (s - RTOT);
    __shared__ float sa[4 * FIN];
    const float* arow = audio + ((long long)b * TIN + t * 4) * FIN;
    for (int i = threadIdx.x; i < 4 * FIN; i += 128) sa[i] = arow[i];
    __syncthreads();
    int fo = threadIdx.x;
    float* xr = x + ((long long)b * SEQ + s) * DM;
    #pragma unroll
    for (int sub = 0; sub < 4; sub++) {
        float acc = bias[fo];
        #pragma unroll 8
        for (int f = 0; f < FIN; f++) acc += sa[sub * FIN + f] * W[f * FOUT + fo];
        xr[sub * FOUT + fo] = acc;
    }
}

// -------- LayerNorm (optionally fused residual add) --------
__global__ void k_ln(const float* __restrict__ in, const float* __restrict__ add,
                     float* __restrict__ out,
                     const float* __restrict__ gg, const float* __restrict__ bb) {
    __shared__ float sh[32];
    long long base = (long long)blockIdx.x * DM;
    int t = threadIdx.x;
    float v0 = in[base + t], v1 = in[base + t + 256];
    if (add) { v0 += add[base + t]; v1 += add[base + t + 256]; }
    float mu  = bsum(v0 + v1, sh) * (1.f / DM);
    float d0 = v0 - mu, d1 = v1 - mu;
    float var = bsum(d0 * d0 + d1 * d1, sh) * (1.f / DM);
    float r = rsqrtf(var + 1e-3f);
    out[base + t]       = d0 * r * gg[t]       + bb[t];
    out[base + t + 256] = d1 * r * gg[t + 256] + bb[t + 256];
}

// -------- row softmax over SEQ --------
__global__ void k_softmax(float* __restrict__ att) {
    __shared__ float sh[32];
    float* row = att + (long long)blockIdx.x * SEQ;
    float m = -3e38f;
    for (int i = threadIdx.x; i < SEQ; i += 256) m = fmaxf(m, row[i]);
    m = bmax(m, sh);
    float s = 0.f;
    for (int i = threadIdx.x; i < SEQ; i += 256) {
        float e = __expf(row[i] - m);
        row[i] = e; s += e;
    }
    s = bsum(s, sh);
    float inv = 1.f / s;
    for (int i = threadIdx.x; i < SEQ; i += 256) row[i] *= inv;
}

// ======== TF32 tensor-core GEMM ========
// C = epilogue(alpha * A@B(^T) + bias), block tile 128x64, BK=16,
// 256 threads = 8 warps (4 along M x 2 along N), warp tile 32x32.
// mma.sync.m16n8k8.tf32, fp32 accumulate.
// mode: 0 store, 1 accumulate into C, 2 relu, 3 attention scale+mask.

__device__ __forceinline__ float totf(float x) {
    unsigned u;
    asm("cvt.rna.tf32.f32 %0, %1;" : "=r"(u) : "f"(x));
    return __uint_as_float(u);
}

__device__ __forceinline__ void mma8(float* c, const unsigned* a, const unsigned* b) {
    asm volatile(
        "mma.sync.aligned.m16n8k8.row.col.f32.tf32.tf32.f32 "
        "{%0,%1,%2,%3}, {%4,%5,%6,%7}, {%8,%9}, {%0,%1,%2,%3};"
        : "+f"(c[0]), "+f"(c[1]), "+f"(c[2]), "+f"(c[3])
        : "r"(a[0]), "r"(a[1]), "r"(a[2]), "r"(a[3]), "r"(b[0]), "r"(b[1]));
}

__global__ __launch_bounds__(256)
void k_gemm(const float* __restrict__ A, int lda, long long sAb, long long sAh,
            const float* __restrict__ B, int ldb, long long sBb, long long sBh,
            float* __restrict__ C, int ldc, long long sCb, long long sCh,
            const float* __restrict__ bias,
            int M, int N, int K, int Hdiv, int mode, float alpha, int transB) {
    __shared__ float As[128][20];   // [m][k], pad -> conflict-free frag loads
    __shared__ float Bs[16][72];    // [k][n]

    int bz = blockIdx.z;
    int bb = bz / Hdiv, hh = bz % Hdiv;
    A += bb * sAb + hh * sAh;
    B += bb * sBb + hh * sBh;
    C += bb * sCb + hh * sCh;

    const int tid  = threadIdx.x;
    const int wid  = tid >> 5, lane = tid & 31;
    const int wm   = wid & 3,  wn   = wid >> 2;
    const int grp  = lane >> 2, tg  = lane & 3;

    float acc[2][4][4];
    #pragma unroll
    for (int mt = 0; mt < 2; mt++)
        #pragma unroll
        for (int nt = 0; nt < 4; nt++)
            #pragma unroll
            for (int i = 0; i < 4; i++) acc[mt][nt][i] = 0.f;

    // A staging: 2 float4 per thread. rows r0, r0+64; k-quad kq.
    const int r0  = tid >> 2;
    const int kq  = (tid & 3) * 4;
    const int gr0 = blockIdx.y * 128 + r0;
    const int gr1 = gr0 + 64;
    // B staging (non-trans): k = tid>>4, n-quad
    const int bk  = tid >> 4;
    const int bnq = (tid & 15) * 4;
    // B staging (trans): n = tid>>2, k-quad = kq
    const int btn = tid >> 2;

    float4 ra0, ra1, rb;
    const float4 z4 = make_float4(0.f, 0.f, 0.f, 0.f);

    bool va0 = gr0 < M, va1 = gr1 < M;
    bool vb;
    if (!transB) vb = (blockIdx.x * 64 + bnq) < N;
    else         vb = (blockIdx.x * 64 + btn) < N;

    // ---- load k-tile into regs ----
    #define LOADREGS(K0)                                                          \
        {                                                                         \
            ra0 = va0 ? *(const float4*)&A[(long long)gr0 * lda + (K0) + kq] : z4;\
            ra1 = va1 ? *(const float4*)&A[(long long)gr1 * lda + (K0) + kq] : z4;\
            if (!transB)                                                          \
                rb = vb ? *(const float4*)&B[(long long)((K0) + bk) * ldb         \
                                             + blockIdx.x * 64 + bnq] : z4;       \
            else                                                                  \
                rb = vb ? *(const float4*)&B[(long long)(blockIdx.x * 64 + btn)   \
                                             * ldb + (K0) + kq] : z4;             \
        }

    #define STORESMEM()                                                           \
        {                                                                         \
            As[r0][kq]          = totf(ra0.x); As[r0][kq + 1]      = totf(ra0.y); \
            As[r0][kq + 2]      = totf(ra0.z); As[r0][kq + 3]      = totf(ra0.w); \
            As[r0 + 64][kq]     = totf(ra1.x); As[r0 + 64][kq + 1] = totf(ra1.y); \
            As[r0 + 64][kq + 2] = totf(ra1.z); As[r0 + 64][kq + 3] = totf(ra1.w); \
            if (!transB) {                                                        \
                Bs[bk][bnq]     = totf(rb.x);  Bs[bk][bnq + 1]     = totf(rb.y);  \
                Bs[bk][bnq + 2] = totf(rb.z);  Bs[bk][bnq + 3]     = totf(rb.w);  \
            } else {                                                              \
                Bs[kq][btn]     = totf(rb.x);  Bs[kq + 1][btn]     = totf(rb.y);  \
                Bs[kq + 2][btn] = totf(rb.z);  Bs[kq + 3][btn]     = totf(rb.w);  \
            }                                                                     \
        }

    LOADREGS(0);
    STORESMEM();
    __syncthreads();

    for (int k0 = 0; k0 < K; k0 += 16) {
        bool more = (k0 + 16) < K;
        if (more) LOADREGS(k0 + 16);

        #pragma unroll
        for (int ks = 0; ks < 2; ks++) {
            const int kb = ks * 8;
            unsigned a[2][4], b[4][2];
            #pragma unroll
            for (int mt = 0; mt < 2; mt++) {
                int mb = wm * 32 + mt * 16;
                a[mt][0] = __float_as_uint(As[mb + grp    ][kb + tg    ]);
                a[mt][1] = __float_as_uint(As[mb + grp + 8][kb + tg    ]);
                a[mt][2] = __float_as_uint(As[mb + grp    ][kb + tg + 4]);
                a[mt][3] = __float_as_uint(As[mb + grp + 8][kb + tg + 4]);
            }
            #pragma unroll
            for (int nt = 0; nt < 4; nt++) {
                int nbs = wn * 32 + nt * 8 + grp;
                b[nt][0] = __float_as_uint(Bs[kb + tg    ][nbs]);
                b[nt][1] = __float_as_uint(Bs[kb + tg + 4][nbs]);
            }
            #pragma unroll
            for (int mt = 0; mt < 2; mt++)
                #pragma unroll
                for (int nt = 0; nt < 4; nt++)
                    mma8(acc[mt][nt], a[mt], b[nt]);
        }
        __syncthreads();
        if (more) {
            STORESMEM();
            __syncthreads();
        }
    }

    // ---- epilogue ----
    #pragma unroll
    for (int mt = 0; mt < 2; mt++) {
        #pragma unroll
        for (int i = 0; i < 2; i++) {
            int row = blockIdx.y * 128 + wm * 32 + mt * 16 + grp + i * 8;
            if (row >= M) continue;
            #pragma unroll
            for (int nt = 0; nt < 4; nt++) {
                #pragma unroll
                for (int j = 0; j < 2; j++) {
                    int col = blockIdx.x * 64 + wn * 32 + nt * 8 + tg * 2 + j;
                    if (col >= N) continue;
                    float v = acc[mt][nt][i * 2 + j] * alpha;
                    if (bias) v += bias[col];
                    long long ci = (long long)row * ldc + col;
                    if (mode == 0)      C[ci] = v;
                    else if (mode == 1) C[ci] += v;
                    else if (mode == 2) C[ci] = fmaxf(v, 0.f);
                    else                C[ci] = emask(row, col) ? v : -1e9f;
                }
            }
        }
    }
    #undef LOADREGS
    #undef STORESMEM
}

// -------- final slice --------
__global__ void k_out(const float* __restrict__ x, float* __restrict__ out) {
    int idx = blockIdx.x * 256 + threadIdx.x;
    int d = idx & (DM - 1);
    int t = (idx >> 9) & (TT - 1);
    int b = idx >> 18;
    out[idx] = x[((long long)b * SEQ + RTOT + t) * DM + d];
}

extern "C" void kernel_launch(void* const* d_in, const int* in_sizes, int n_in,
                              void* d_out, int out_size) {
    const float* audio   = (const float*)d_in[0];
    const float* W_in    = (const float*)d_in[1];
    const float* b_in    = (const float*)d_in[2];
    const float* ln_in_g = (const float*)d_in[3];
    const float* ln_in_b = (const float*)d_in[4];
    const float* Wq = (const float*)d_in[5];
    const float* bq = (const float*)d_in[6];
    const float* Wk = (const float*)d_in[7];
    const float* bk = (const float*)d_in[8];
    const float* Wv = (const float*)d_in[9];
    const float* bv = (const float*)d_in[10];
    const float* Wo = (const float*)d_in[11];
    const float* bo = (const float*)d_in[12];
    const float* ln1_g = (const float*)d_in[13];
    const float* ln1_b = (const float*)d_in[14];
    const float* W1 = (const float*)d_in[15];
    const float* b1 = (const float*)d_in[16];
    const float* W2 = (const float*)d_in[17];
    const float* b2 = (const float*)d_in[18];
    const float* ln2_g = (const float*)d_in[19];
    const float* ln2_b = (const float*)d_in[20];
    (void)in_sizes; (void)n_in; (void)out_size;

    float *x, *y, *qb, *kb, *vb, *att, *ffn;
    cudaGetSymbolAddress((void**)&x,   g_x);
    cudaGetSymbolAddress((void**)&y,   g_y);
    cudaGetSymbolAddress((void**)&qb,  g_q);
    cudaGetSymbolAddress((void**)&kb,  g_k);
    cudaGetSymbolAddress((void**)&vb,  g_v);
    cudaGetSymbolAddress((void**)&att, g_att);
    cudaGetSymbolAddress((void**)&ffn, g_ffn);

    const int M = NB * SEQ;                           // 4992
    const long long sBD = (long long)SEQ * DM;
    const long long sAttB = (long long)NH * SEQ * SEQ;
    const long long sAttH = (long long)SEQ * SEQ;

    k_input<<<dim3(SEQ, NB), 128>>>(audio, W_in, b_in, x);

    for (int l = 0; l < NLAYERS; l++) {
        const float* wq = Wq + (long long)l * DM * DM;
        const float* wk = Wk + (long long)l * DM * DM;
        const float* wv = Wv + (long long)l * DM * DM;
        const float* wo = Wo + (long long)l * DM * DM;
        const float* w1 = W1 + (long long)l * DM * DFF;
        const float* w2 = W2 + (long long)l * DFF * DM;

        k_ln<<<M, 256>>>(x, nullptr, y, ln_in_g + l * DM, ln_in_b + l * DM);

        k_gemm<<<dim3(8, 39, 1), 256>>>(y, DM, 0, 0, wq, DM, 0, 0, qb, DM, 0, 0,
                                        bq + l * DM, M, DM, DM, 1, 0, 1.f, 0);
        k_gemm<<<dim3(8, 39, 1), 256>>>(y, DM, 0, 0, wk, DM, 0, 0, kb, DM, 0, 0,
                                        bk + l * DM, M, DM, DM, 1, 0, 1.f, 0);
        k_gemm<<<dim3(8, 39, 1), 256>>>(y, DM, 0, 0, wv, DM, 0, 0, vb, DM, 0, 0,
                                        bv + l * DM, M, DM, DM, 1, 0, 1.f, 0);

        // scores = (Q @ K^T) / 8, masked
        k_gemm<<<dim3(10, 5, NB * NH), 256>>>(qb, DM, sBD, HSZ, kb, DM, sBD, HSZ,
                                              att, SEQ, sAttB, sAttH,
                                              nullptr, SEQ, SEQ, HSZ, NH, 3, 0.125f, 1);
        k_softmax<<<NB * NH * SEQ, 256>>>(att);

        // context = P @ V
        k_gemm<<<dim3(1, 5, NB * NH), 256>>>(att, SEQ, sAttB, sAttH, vb, DM, sBD, HSZ,
                                             y, DM, sBD, HSZ,
                                             nullptr, SEQ, HSZ, SEQ, NH, 0, 1.f, 0);

        // x += ctx @ Wo + bo
        k_gemm<<<dim3(8, 39, 1), 256>>>(y, DM, 0, 0, wo, DM, 0, 0, x, DM, 0, 0,
                                        bo + l * DM, M, DM, DM, 1, 1, 1.f, 0);

        // FFN
        k_ln<<<M, 256>>>(x, nullptr, y, ln1_g + l * DM, ln1_b + l * DM);
        k_gemm<<<dim3(32, 39, 1), 256>>>(y, DM, 0, 0, w1, DFF, 0, 0, ffn, DFF, 0, 0,
                                         b1 + l * DFF, M, DFF, DM, 1, 2, 1.f, 0);
        k_gemm<<<dim3(8, 39, 1), 256>>>(ffn, DFF, 0, 0, w2, DM, 0, 0, qb, DM, 0, 0,
                                        b2 + l * DM, M, DM, DFF, 1, 0, 1.f, 0);

        k_ln<<<M, 256>>>(x, qb, x, ln2_g + l * DM, ln2_b + l * DM);
    }

    k_out<<<(NB * TT * DM) / 256, 256>>>(x, (float*)d_out);
}

// round 3
// speedup vs baseline: 3.2500x; 1.0035x over previous
#include <cuda_runtime.h>
#include <math.h>

#define NB   8
#define TIN  2048
#define FIN  80
#define FOUT 128
#define TT   512
#define SEQ  624
#define DM   512
#define NH   8
#define HSZ  64
#define DFF  2048
#define RTOT 112
#define NLAYERS 4

// -------- scratch (static device globals; no allocations) --------
static __device__ float g_x  [NB*SEQ*DM];
static __device__ float g_y  [NB*SEQ*DM];
static __device__ float g_q  [NB*SEQ*DM];
static __device__ float g_k  [NB*SEQ*DM];
static __device__ float g_v  [NB*SEQ*DM];
static __device__ float g_att[NB*NH*SEQ*SEQ];
static __device__ float g_ffn[NB*SEQ*DFF];

// -------- Emformer mask, computed analytically --------
__device__ __forceinline__ bool emask(int qs, int ks) {
    int ci;
    if (qs < RTOT) {
        ci = qs >> 4;
        if (ks < RTOT) return (ks >> 4) == ci;
    } else {
        ci = (qs - RTOT) >> 6;
        if (ks < RTOT) return ((ks >> 4) == ci) && (ci < 7);
    }
    int k  = ks - RTOT;
    int lo = ci * 64 - 32; if (lo < 0)  lo = 0;
    int hi = (ci + 1) * 64; if (hi > TT) hi = TT;
    return (k >= lo) && (k < hi);
}

// -------- block reductions --------
__device__ __forceinline__ float bsum(float v, float* sh) {
    int lane = threadIdx.x & 31, w = threadIdx.x >> 5;
    #pragma unroll
    for (int o = 16; o; o >>= 1) v += __shfl_xor_sync(0xffffffffu, v, o);
    if (lane == 0) sh[w] = v;
    __syncthreads();
    if (threadIdx.x < 32) {
        float t = (threadIdx.x < (blockDim.x >> 5)) ? sh[threadIdx.x] : 0.f;
        #pragma unroll
        for (int o = 16; o; o >>= 1) t += __shfl_xor_sync(0xffffffffu, t, o);
        if (threadIdx.x == 0) sh[0] = t;
    }
    __syncthreads();
    float r = sh[0];
    __syncthreads();
    return r;
}

__device__ __forceinline__ float bmax(float v, float* sh) {
    int lane = threadIdx.x & 31, w = threadIdx.x >> 5;
    #pragma unroll
    for (int o = 16; o; o >>= 1) v = fmaxf(v, __shfl_xor_sync(0xffffffffu, v, o));
    if (lane == 0) sh[w] = v;
    __syncthreads();
    if (threadIdx.x < 32) {
        float t = (threadIdx.x < (blockDim.x >> 5)) ? sh[threadIdx.x] : -3e38f;
        #pragma unroll
        for (int o = 16; o; o >>= 1) t = fmaxf(t, __shfl_xor_sync(0xffffffffu, t, o));
        if (threadIdx.x == 0) sh[0] = t;
    }
    __syncthreads();
    float r = sh[0];
    __syncthreads();
    return r;
}

// -------- input dense + stack-subsample + right-context gather --------
__global__ void k_input(const float* __restrict__ audio,
                        const float* __restrict__ W,
                        const float* __restrict__ bias,
                        float* __restrict__ x) {
    int b = blockIdx.y, s = blockIdx.x;
    int t = (s < RTOT) ? (((s >> 4) + 1) * 64 + (s & 15)) : (s - RTOT);
    __shared__ float sa[4 * FIN];
    const float* arow = audio + ((long long)b * TIN + t * 4) * FIN;
    for (int i = threadIdx.x; i < 4 * FIN; i += 128) sa[i] = arow[i];
    __syncthreads();
    int fo = threadIdx.x;
    float* xr = x + ((long long)b * SEQ + s) * DM;
    #pragma unroll
    for (int sub = 0; sub < 4; sub++) {
        float acc = bias[fo];
        #pragma unroll 8
        for (int f = 0; f < FIN; f++) acc += sa[sub * FIN + f] * W[f * FOUT + fo];
        xr[sub * FOUT + fo] = acc;
    }
}

// -------- LayerNorm (optionally fused residual add) --------
__global__ void k_ln(const float* __restrict__ in, const float* __restrict__ add,
                     float* __restrict__ out,
                     const float* __restrict__ gg, const float* __restrict__ bb) {
    __shared__ float sh[32];
    long long base = (long long)blockIdx.x * DM;
    int t = threadIdx.x;
    float v0 = in[base + t], v1 = in[base + t + 256];
    if (add) { v0 += add[base + t]; v1 += add[base + t + 256]; }
    float mu  = bsum(v0 + v1, sh) * (1.f / DM);
    float d0 = v0 - mu, d1 = v1 - mu;
    float var = bsum(d0 * d0 + d1 * d1, sh) * (1.f / DM);
    float r = rsqrtf(var + 1e-3f);
    out[base + t]       = d0 * r * gg[t]       + bb[t];
    out[base + t + 256] = d1 * r * gg[t + 256] + bb[t + 256];
}

// -------- row softmax over SEQ --------
__global__ void k_softmax(float* __restrict__ att) {
    __shared__ float sh[32];
    float* row = att + (long long)blockIdx.x * SEQ;
    float m = -3e38f;
    for (int i = threadIdx.x; i < SEQ; i += 256) m = fmaxf(m, row[i]);
    m = bmax(m, sh);
    float s = 0.f;
    for (int i = threadIdx.x; i < SEQ; i += 256) {
        float e = __expf(row[i] - m);
        row[i] = e; s += e;
    }
    s = bsum(s, sh);
    float inv = 1.f / s;
    for (int i = threadIdx.x; i < SEQ; i += 256) row[i] *= inv;
}

// ======== TF32 tensor-core GEMM ========
// C = epilogue(alpha * A@B(^T) + bias), block tile 128x64, BK=16,
// 256 threads = 8 warps (4 along M x 2 along N), warp tile 32x32.
// mma.sync.m16n8k8.tf32, fp32 accumulate.
// mode: 0 store, 1 accumulate into C, 2 relu, 3 attention scale+mask.

__device__ __forceinline__ float totf(float x) {
    unsigned u;
    asm("cvt.rna.tf32.f32 %0, %1;" : "=r"(u) : "f"(x));
    return __uint_as_float(u);
}

__device__ __forceinline__ void mma8(float* c, const unsigned* a, const unsigned* b) {
    asm volatile(
        "mma.sync.aligned.m16n8k8.row.col.f32.tf32.tf32.f32 "
        "{%0,%1,%2,%3}, {%4,%5,%6,%7}, {%8,%9}, {%0,%1,%2,%3};"
        : "+f"(c[0]), "+f"(c[1]), "+f"(c[2]), "+f"(c[3])
        : "r"(a[0]), "r"(a[1]), "r"(a[2]), "r"(a[3]), "r"(b[0]), "r"(b[1]));
}

__global__ __launch_bounds__(256)
void k_gemm(const float* __restrict__ A, int lda, long long sAb, long long sAh,
            const float* __restrict__ B, int ldb, long long sBb, long long sBh,
            float* __restrict__ C, int ldc, long long sCb, long long sCh,
            const float* __restrict__ bias,
            int M, int N, int K, int Hdiv, int mode, float alpha, int transB) {
    __shared__ float As[128][20];   // [m][k], pad -> conflict-free frag loads
    __shared__ float Bs[16][72];    // [k][n]

    int bz = blockIdx.z;
    int bb = bz / Hdiv, hh = bz % Hdiv;
    A += bb * sAb + hh * sAh;
    B += bb * sBb + hh * sBh;
    C += bb * sCb + hh * sCh;

    const int tid  = threadIdx.x;
    const int wid  = tid >> 5, lane = tid & 31;
    const int wm   = wid & 3,  wn   = wid >> 2;
    const int grp  = lane >> 2, tg  = lane & 3;

    float acc[2][4][4];
    #pragma unroll
    for (int mt = 0; mt < 2; mt++)
        #pragma unroll
        for (int nt = 0; nt < 4; nt++)
            #pragma unroll
            for (int i = 0; i < 4; i++) acc[mt][nt][i] = 0.f;

    // A staging: 2 float4 per thread. rows r0, r0+64; k-quad kq.
    const int r0  = tid >> 2;
    const int kq  = (tid & 3) * 4;
    const int gr0 = blockIdx.y * 128 + r0;
    const int gr1 = gr0 + 64;
    // B staging (non-trans): k = tid>>4, n-quad
    const int bk  = tid >> 4;
    const int bnq = (tid & 15) * 4;
    // B staging (trans): n = tid>>2, k-quad = kq
    const int btn = tid >> 2;

    float4 ra0, ra1, rb;
    const float4 z4 = make_float4(0.f, 0.f, 0.f, 0.f);

    bool va0 = gr0 < M, va1 = gr1 < M;
    bool vb;
    if (!transB) vb = (blockIdx.x * 64 + bnq) < N;
    else         vb = (blockIdx.x * 64 + btn) < N;

    // ---- load k-tile into regs ----
    #define LOADREGS(K0)                                                          \
        {                                                                         \
            ra0 = va0 ? *(const float4*)&A[(long long)gr0 * lda + (K0) + kq] : z4;\
            ra1 = va1 ? *(const float4*)&A[(long long)gr1 * lda + (K0) + kq] : z4;\
            if (!transB)                                                          \
                rb = vb ? *(const float4*)&B[(long long)((K0) + bk) * ldb         \
                                             + blockIdx.x * 64 + bnq] : z4;       \
            else                                                                  \
                rb = vb ? *(const float4*)&B[(long long)(blockIdx.x * 64 + btn)   \
                                             * ldb + (K0) + kq] : z4;             \
        }

    #define STORESMEM()                                                           \
        {                                                                         \
            As[r0][kq]          = totf(ra0.x); As[r0][kq + 1]      = totf(ra0.y); \
            As[r0][kq + 2]      = totf(ra0.z); As[r0][kq + 3]      = totf(ra0.w); \
            As[r0 + 64][kq]     = totf(ra1.x); As[r0 + 64][kq + 1] = totf(ra1.y); \
            As[r0 + 64][kq + 2] = totf(ra1.z); As[r0 + 64][kq + 3] = totf(ra1.w); \
            if (!transB) {                                                        \
                Bs[bk][bnq]     = totf(rb.x);  Bs[bk][bnq + 1]     = totf(rb.y);  \
                Bs[bk][bnq + 2] = totf(rb.z);  Bs[bk][bnq + 3]     = totf(rb.w);  \
            } else {                                                              \
                Bs[kq][btn]     = totf(rb.x);  Bs[kq + 1][btn]     = totf(rb.y);  \
                Bs[kq + 2][btn] = totf(rb.z);  Bs[kq + 3][btn]     = totf(rb.w);  \
            }                                                                     \
        }

    LOADREGS(0);
    STORESMEM();
    __syncthreads();

    for (int k0 = 0; k0 < K; k0 += 16) {
        bool more = (k0 + 16) < K;
        if (more) LOADREGS(k0 + 16);

        #pragma unroll
        for (int ks = 0; ks < 2; ks++) {
            const int kb = ks * 8;
            unsigned a[2][4], b[4][2];
            #pragma unroll
            for (int mt = 0; mt < 2; mt++) {
                int mb = wm * 32 + mt * 16;
                a[mt][0] = __float_as_uint(As[mb + grp    ][kb + tg    ]);
                a[mt][1] = __float_as_uint(As[mb + grp + 8][kb + tg    ]);
                a[mt][2] = __float_as_uint(As[mb + grp    ][kb + tg + 4]);
                a[mt][3] = __float_as_uint(As[mb + grp + 8][kb + tg + 4]);
            }
            #pragma unroll
            for (int nt = 0; nt < 4; nt++) {
                int nbs = wn * 32 + nt * 8 + grp;
                b[nt][0] = __float_as_uint(Bs[kb + tg    ][nbs]);
                b[nt][1] = __float_as_uint(Bs[kb + tg + 4][nbs]);
            }
            #pragma unroll
            for (int mt = 0; mt < 2; mt++)
                #pragma unroll
                for (int nt = 0; nt < 4; nt++)
                    mma8(acc[mt][nt], a[mt], b[nt]);
        }
        __syncthreads();
        if (more) {
            STORESMEM();
            __syncthreads();
        }
    }

    // ---- epilogue ----
    #pragma unroll
    for (int mt = 0; mt < 2; mt++) {
        #pragma unroll
        for (int i = 0; i < 2; i++) {
            int row = blockIdx.y * 128 + wm * 32 + mt * 16 + grp + i * 8;
            if (row >= M) continue;
            #pragma unroll
            for (int nt = 0; nt < 4; nt++) {
                #pragma unroll
                for (int j = 0; j < 2; j++) {
                    int col = blockIdx.x * 64 + wn * 32 + nt * 8 + tg * 2 + j;
                    if (col >= N) continue;
                    float v = acc[mt][nt][i * 2 + j] * alpha;
                    if (bias) v += bias[col];
                    long long ci = (long long)row * ldc + col;
                    if (mode == 0)      C[ci] = v;
                    else if (mode == 1) C[ci] += v;
                    else if (mode == 2) C[ci] = fmaxf(v, 0.f);
                    else                C[ci] = emask(row, col) ? v : -1e9f;
                }
            }
        }
    }
    #undef LOADREGS
    #undef STORESMEM
}

// -------- final slice --------
__global__ void k_out(const float* __restrict__ x, float* __restrict__ out) {
    int idx = blockIdx.x * 256 + threadIdx.x;
    int d = idx & (DM - 1);
    int t = (idx >> 9) & (TT - 1);
    int b = idx >> 18;
    out[idx] = x[((long long)b * SEQ + RTOT + t) * DM + d];
}

extern "C" void kernel_launch(void* const* d_in, const int* in_sizes, int n_in,
                              void* d_out, int out_size) {
    const float* audio   = (const float*)d_in[0];
    const float* W_in    = (const float*)d_in[1];
    const float* b_in    = (const float*)d_in[2];
    const float* ln_in_g = (const float*)d_in[3];
    const float* ln_in_b = (const float*)d_in[4];
    const float* Wq = (const float*)d_in[5];
    const float* bq = (const float*)d_in[6];
    const float* Wk = (const float*)d_in[7];
    const float* bk = (const float*)d_in[8];
    const float* Wv = (const float*)d_in[9];
    const float* bv = (const float*)d_in[10];
    const float* Wo = (const float*)d_in[11];
    const float* bo = (const float*)d_in[12];
    const float* ln1_g = (const float*)d_in[13];
    const float* ln1_b = (const float*)d_in[14];
    const float* W1 = (const float*)d_in[15];
    const float* b1 = (const float*)d_in[16];
    const float* W2 = (const float*)d_in[17];
    const float* b2 = (const float*)d_in[18];
    const float* ln2_g = (const float*)d_in[19];
    const float* ln2_b = (const float*)d_in[20];
    (void)in_sizes; (void)n_in; (void)out_size;

    float *x, *y, *qb, *kb, *vb, *att, *ffn;
    cudaGetSymbolAddress((void**)&x,   g_x);
    cudaGetSymbolAddress((void**)&y,   g_y);
    cudaGetSymbolAddress((void**)&qb,  g_q);
    cudaGetSymbolAddress((void**)&kb,  g_k);
    cudaGetSymbolAddress((void**)&vb,  g_v);
    cudaGetSymbolAddress((void**)&att, g_att);
    cudaGetSymbolAddress((void**)&ffn, g_ffn);

    const int M = NB * SEQ;                           // 4992
    const long long sBD = (long long)SEQ * DM;
    const long long sAttB = (long long)NH * SEQ * SEQ;
    const long long sAttH = (long long)SEQ * SEQ;

    k_input<<<dim3(SEQ, NB), 128>>>(audio, W_in, b_in, x);

    for (int l = 0; l < NLAYERS; l++) {
        const float* wq = Wq + (long long)l * DM * DM;
        const float* wk = Wk + (long long)l * DM * DM;
        const float* wv = Wv + (long long)l * DM * DM;
        const float* wo = Wo + (long long)l * DM * DM;
        const float* w1 = W1 + (long long)l * DM * DFF;
        const float* w2 = W2 + (long long)l * DFF * DM;

        k_ln<<<M, 256>>>(x, nullptr, y, ln_in_g + l * DM, ln_in_b + l * DM);

        k_gemm<<<dim3(8, 39, 1), 256>>>(y, DM, 0, 0, wq, DM, 0, 0, qb, DM, 0, 0,
                                        bq + l * DM, M, DM, DM, 1, 0, 1.f, 0);
        k_gemm<<<dim3(8, 39, 1), 256>>>(y, DM, 0, 0, wk, DM, 0, 0, kb, DM, 0, 0,
                                        bk + l * DM, M, DM, DM, 1, 0, 1.f, 0);
        k_gemm<<<dim3(8, 39, 1), 256>>>(y, DM, 0, 0, wv, DM, 0, 0, vb, DM, 0, 0,
                                        bv + l * DM, M, DM, DM, 1, 0, 1.f, 0);

        // scores = (Q @ K^T) / 8, masked
        k_gemm<<<dim3(10, 5, NB * NH), 256>>>(qb, DM, sBD, HSZ, kb, DM, sBD, HSZ,
                                              att, SEQ, sAttB, sAttH,
                                              nullptr, SEQ, SEQ, HSZ, NH, 3, 0.125f, 1);
        k_softmax<<<NB * NH * SEQ, 256>>>(att);

        // context = P @ V
        k_gemm<<<dim3(1, 5, NB * NH), 256>>>(att, SEQ, sAttB, sAttH, vb, DM, sBD, HSZ,
                                             y, DM, sBD, HSZ,
                                             nullptr, SEQ, HSZ, SEQ, NH, 0, 1.f, 0);

        // x += ctx @ Wo + bo
        k_gemm<<<dim3(8, 39, 1), 256>>>(y, DM, 0, 0, wo, DM, 0, 0, x, DM, 0, 0,
                                        bo + l * DM, M, DM, DM, 1, 1, 1.f, 0);

        // FFN
        k_ln<<<M, 256>>>(x, nullptr, y, ln1_g + l * DM, ln1_b + l * DM);
        k_gemm<<<dim3(32, 39, 1), 256>>>(y, DM, 0, 0, w1, DFF, 0, 0, ffn, DFF, 0, 0,
                                         b1 + l * DFF, M, DFF, DM, 1, 2, 1.f, 0);
        k_gemm<<<dim3(8, 39, 1), 256>>>(ffn, DFF, 0, 0, w2, DM, 0, 0, qb, DM, 0, 0,
                                        b2 + l * DM, M, DM, DFF, 1, 0, 1.f, 0);

        k_ln<<<M, 256>>>(x, qb, x, ln2_g + l * DM, ln2_b + l * DM);
    }

    k_out<<<(NB * TT * DM) / 256, 256>>>(x, (float*)d_out);
}